// round 1
// baseline (speedup 1.0000x reference)
#include <cuda_runtime.h>
#include <cstdint>
#include <cstddef>

#define NPEDS 65536
#define HDIM  128
#define EDIM  64
#define KDIM  192      // EDIM + HDIM
#define GATES 512      // 4 * HDIM
#define STEPS 12
#define PEDS_PER_CTA 16
#define XS    20       // x_sh row stride in floats (80B: 16B-aligned, low STS conflicts)

// Transposed combined weights: W_T[k][j] = row j of [w_ih | w_hh], column k.
__device__ float g_WT[KDIM * GATES];
__device__ float g_b[GATES];           // b_ih + b_hh

__global__ void prep_kernel(const float* __restrict__ w_ih, const float* __restrict__ w_hh,
                            const float* __restrict__ b_ih, const float* __restrict__ b_hh) {
    int idx = blockIdx.x * blockDim.x + threadIdx.x;
    if (idx < KDIM * GATES) {
        int k = idx / GATES;
        int j = idx % GATES;
        g_WT[idx] = (k < EDIM) ? w_ih[j * EDIM + k] : w_hh[j * HDIM + (k - EDIM)];
    }
    if (idx < GATES) g_b[idx] = b_ih[idx] + b_hh[idx];
}

__device__ __forceinline__ unsigned long long pack2(float lo, float hi) {
    unsigned long long v;
    asm("mov.b64 %0, {%1,%2};" : "=l"(v) : "f"(lo), "f"(hi));
    return v;
}
__device__ __forceinline__ void unpack2(unsigned long long v, float& lo, float& hi) {
    asm("mov.b64 {%0,%1}, %2;" : "=f"(lo), "=f"(hi) : "l"(v));
}
// Packed dual-FMA (sm_100 f32x2 path -> FFMA2 in SASS)
__device__ __forceinline__ unsigned long long ffma2(unsigned long long a,
                                                    unsigned long long b,
                                                    unsigned long long c) {
    unsigned long long d;
    asm("fma.rn.f32x2 %0, %1, %2, %3;" : "=l"(d) : "l"(a), "l"(b), "l"(c));
    return d;
}
__device__ __forceinline__ float sig_f(float x)  { return __fdividef(1.f, 1.f + __expf(-x)); }
__device__ __forceinline__ float tanh_f(float x) { return __fdividef(2.f, 1.f + __expf(-2.f * x)) - 1.f; }

__global__ __launch_bounds__(128)
void decoder_kernel(const float* __restrict__ lpr,   // last_pos_rel [N,2]
                    const float* __restrict__ h0,    // [N,128]
                    const float* __restrict__ c0,    // [N,128]
                    const float* __restrict__ w_se,  // [64,2]
                    const float* __restrict__ b_se,  // [64]
                    const float* __restrict__ w_hp,  // [2,128]
                    const float* __restrict__ b_hp,  // [2]
                    float* __restrict__ out)         // [12,N,2]
{
    __shared__ __align__(16) float x_sh[KDIM * XS];  // [k][ped], x = [dec_in | h]
    __shared__ float whp_sh[2 * HDIM];
    __shared__ float wse_sh[EDIM * 2];
    __shared__ float bse_sh[EDIM];
    __shared__ float bhp_sh[2];

    const int tid = threadIdx.x;          // 0..127 == LSTM unit index u
    const int pedbase = blockIdx.x * PEDS_PER_CTA;

    // ---- small weights into smem ----
    for (int i = tid; i < 2 * HDIM; i += 128) whp_sh[i] = w_hp[i];
    for (int i = tid; i < EDIM * 2; i += 128) wse_sh[i] = w_se[i];
    if (tid < EDIM) bse_sh[tid] = b_se[tid];
    if (tid < 2)    bhp_sh[tid] = b_hp[tid];

    // ---- per-thread constants / state ----
    unsigned long long binit[4];
#pragma unroll
    for (int r = 0; r < 4; r++) {
        float b = g_b[tid + 128 * r];
        binit[r] = pack2(b, b);
    }
    float c_reg[PEDS_PER_CTA];
#pragma unroll
    for (int p = 0; p < PEDS_PER_CTA; p++)
        c_reg[p] = c0[(size_t)(pedbase + p) * HDIM + tid];

    // h part of x
#pragma unroll
    for (int p = 0; p < PEDS_PER_CTA; p++)
        x_sh[(EDIM + tid) * XS + p] = h0[(size_t)(pedbase + p) * HDIM + tid];
    __syncthreads();

    // dec_in0 = last_pos_rel @ w_se^T + b_se   (8 threads per ped)
    {
        int p = tid >> 3, sub = tid & 7;
        float rx = lpr[2 * (pedbase + p)];
        float ry = lpr[2 * (pedbase + p) + 1];
#pragma unroll
        for (int jj = 0; jj < 8; jj++) {
            int e = sub + 8 * jj;
            x_sh[e * XS + p] = rx * wse_sh[2 * e] + ry * wse_sh[2 * e + 1] + bse_sh[e];
        }
    }
    __syncthreads();

    // =================== 12 recurrent steps ===================
    for (int st = 0; st < STEPS; st++) {
        // ---- gates: acc[r][pair] over K=192, rows (tid + 128r) ----
        unsigned long long acc[4][8];
#pragma unroll
        for (int r = 0; r < 4; r++)
#pragma unroll
            for (int q = 0; q < 8; q++) acc[r][q] = binit[r];

#pragma unroll 4
        for (int k = 0; k < KDIM; k++) {
            const float* wrow = &g_WT[k * GATES + tid];
            unsigned long long wp[4];
#pragma unroll
            for (int r = 0; r < 4; r++) {
                float w = __ldg(wrow + 128 * r);
                wp[r] = pack2(w, w);
            }
            const ulonglong2* xk = reinterpret_cast<const ulonglong2*>(x_sh + k * XS);
#pragma unroll
            for (int q = 0; q < 4; q++) {
                ulonglong2 xv = xk[q];
#pragma unroll
                for (int r = 0; r < 4; r++) {
                    acc[r][2 * q]     = ffma2(wp[r], xv.x, acc[r][2 * q]);
                    acc[r][2 * q + 1] = ffma2(wp[r], xv.y, acc[r][2 * q + 1]);
                }
            }
        }
        __syncthreads();   // all x_sh reads done before h is overwritten

        // ---- LSTM elementwise (thread u owns unit u of all 16 peds) ----
        float h_loc[PEDS_PER_CTA];
#pragma unroll
        for (int q = 0; q < 8; q++) {
            float i0, i1, f0, f1, g0, g1, o0, o1;
            unpack2(acc[0][q], i0, i1);
            unpack2(acc[1][q], f0, f1);
            unpack2(acc[2][q], g0, g1);
            unpack2(acc[3][q], o0, o1);
            float cA = sig_f(f0) * c_reg[2 * q]     + sig_f(i0) * tanh_f(g0);
            float cB = sig_f(f1) * c_reg[2 * q + 1] + sig_f(i1) * tanh_f(g1);
            c_reg[2 * q] = cA;
            c_reg[2 * q + 1] = cB;
            h_loc[2 * q]     = sig_f(o0) * tanh_f(cA);
            h_loc[2 * q + 1] = sig_f(o1) * tanh_f(cB);
        }
#pragma unroll
        for (int p = 0; p < PEDS_PER_CTA; p++)
            x_sh[(EDIM + tid) * XS + p] = h_loc[p];
        __syncthreads();

        // ---- rel = h @ w_hp^T + b_hp ; out ; dec_in = rel @ w_se^T + b_se ----
        {
            int p = tid >> 3, sub = tid & 7;
            float ax = 0.f, ay = 0.f;
#pragma unroll
            for (int i = 0; i < 16; i++) {
                int u = sub + 8 * i;
                float h = x_sh[(EDIM + u) * XS + p];
                ax += h * whp_sh[u];
                ay += h * whp_sh[HDIM + u];
            }
#pragma unroll
            for (int off = 4; off >= 1; off >>= 1) {
                ax += __shfl_down_sync(0xffffffffu, ax, off, 8);
                ay += __shfl_down_sync(0xffffffffu, ay, off, 8);
            }
            float rx = __shfl_sync(0xffffffffu, ax, 0, 8) + bhp_sh[0];
            float ry = __shfl_sync(0xffffffffu, ay, 0, 8) + bhp_sh[1];
            if (sub == 0) {
                float2 o2 = make_float2(rx, ry);
                *reinterpret_cast<float2*>(
                    &out[((size_t)st * NPEDS + pedbase + p) * 2]) = o2;
            }
#pragma unroll
            for (int jj = 0; jj < 8; jj++) {
                int e = sub + 8 * jj;
                x_sh[e * XS + p] = rx * wse_sh[2 * e] + ry * wse_sh[2 * e + 1] + bse_sh[e];
            }
        }
        __syncthreads();
    }
}

extern "C" void kernel_launch(void* const* d_in, const int* in_sizes, int n_in,
                              void* d_out, int out_size) {
    (void)in_sizes; (void)n_in; (void)out_size;
    // metadata order: last_pos, last_pos_rel, h0, c0, w_ih, w_hh, b_ih, b_hh,
    //                 w_se, b_se, w_hp, b_hp   (last_pos never affects rels)
    const float* lpr  = (const float*)d_in[1];
    const float* h0   = (const float*)d_in[2];
    const float* c0   = (const float*)d_in[3];
    const float* w_ih = (const float*)d_in[4];
    const float* w_hh = (const float*)d_in[5];
    const float* b_ih = (const float*)d_in[6];
    const float* b_hh = (const float*)d_in[7];
    const float* w_se = (const float*)d_in[8];
    const float* b_se = (const float*)d_in[9];
    const float* w_hp = (const float*)d_in[10];
    const float* b_hp = (const float*)d_in[11];
    float* out = (float*)d_out;

    prep_kernel<<<(KDIM * GATES + 255) / 256, 256>>>(w_ih, w_hh, b_ih, b_hh);
    decoder_kernel<<<NPEDS / PEDS_PER_CTA, 128>>>(lpr, h0, c0, w_se, b_se, w_hp, b_hp, out);
}

// round 3
// speedup vs baseline: 6.3290x; 6.3290x over previous
#include <cuda_runtime.h>
#include <cuda_fp16.h>
#include <cstdint>
#include <cstddef>

#define THREADS 512
#define M_TILE  64
#define NTILES  1024          // 65536 / 64
#define GRID    148
#define STEPS   12
#define KD      128
#define KK_STEPS 8            // 128 / 16

// ---- smem layout (bytes from dynamic base) ----
#define OFF_W    0            // 512 rows * 256B (fp16 swizzled)   = 131072
#define OFF_X    131072       // 64 rows * 256B (h, fp16 swizzled) =  16384
#define OFF_WEFF 147456       // float4[512]                        =   8192
#define OFF_WHP  155648       // float[256]                         =   1024
#define OFF_PART 156672       // float[64][4][2]                    =   2048
#define OFF_REL  158720       // float2[64]                         =    512
#define OFF_BHP  159232       // float[2]                           =      8
#define SMEM_BYTES 159744

__device__ __forceinline__ uint32_t smem_u32(const void* p) {
    uint32_t a;
    asm("{ .reg .u64 t; cvta.to.shared.u64 t, %1; cvt.u32.u64 %0, t; }" : "=r"(a) : "l"(p));
    return a;
}
__device__ __forceinline__ uint32_t packh2(float lo, float hi) {
    uint32_t r; asm("cvt.rn.f16x2.f32 %0, %1, %2;" : "=r"(r) : "f"(hi), "f"(lo)); return r;
}
__device__ __forceinline__ float tanh_ap(float x) {
    float y; asm("tanh.approx.f32 %0, %1;" : "=f"(y) : "f"(x)); return y;
}
// sigmoid via tanh.approx (1 MUFU): abs err ~2.5e-4
__device__ __forceinline__ float siga(float x) { return fmaf(tanh_ap(0.5f * x), 0.5f, 0.5f); }
// accurate tanh via ex2 + rcp (2 MUFU): ~1e-6 — used on the recurrence-critical path
__device__ __forceinline__ float tanhacc(float x) {
    float t = __expf(-2.f * x);
    return __fdividef(2.f, 1.f + t) - 1.f;
}

#define LDSM_X4(r0, r1, r2, r3, addr)                                                  \
    asm volatile("ldmatrix.sync.aligned.m8n8.x4.shared.b16 {%0,%1,%2,%3}, [%4];"       \
                 : "=r"(r0), "=r"(r1), "=r"(r2), "=r"(r3) : "r"(addr))

#define MMA16816(d, a0, a1, a2, a3, b0, b1)                                            \
    asm volatile("mma.sync.aligned.m16n8k16.row.col.f32.f16.f16.f32 "                  \
                 "{%0,%1,%2,%3}, {%4,%5,%6,%7}, {%8,%9}, {%0,%1,%2,%3};"               \
                 : "+f"((d)[0]), "+f"((d)[1]), "+f"((d)[2]), "+f"((d)[3])              \
                 : "r"(a0), "r"(a1), "r"(a2), "r"(a3), "r"(b0), "r"(b1))

// swizzled byte offset within a 256B-row tile: chunk XOR (row & 7)
__device__ __forceinline__ uint32_t swz_off(int r, int k) {
    return (uint32_t)(r * 256 + ((((k >> 3) ^ (r & 7)) << 4) | ((k & 7) * 2)));
}

__global__ __launch_bounds__(THREADS, 1)
void decoder_mma(const float* __restrict__ lpr, const float* __restrict__ h0,
                 const float* __restrict__ c0,
                 const float* __restrict__ w_ih, const float* __restrict__ w_hh,
                 const float* __restrict__ b_ih, const float* __restrict__ b_hh,
                 const float* __restrict__ w_se, const float* __restrict__ b_se,
                 const float* __restrict__ w_hp, const float* __restrict__ b_hp,
                 float2* __restrict__ out)
{
    extern __shared__ char S[];
    const uint32_t Sb = smem_u32(S);
    const uint32_t Xs = Sb + OFF_X;
    float4* weff4 = (float4*)(S + OFF_WEFF);
    float*  whp   = (float*)(S + OFF_WHP);
    float*  part  = (float*)(S + OFF_PART);
    float2* relb  = (float2*)(S + OFF_REL);
    float*  bhp   = (float*)(S + OFF_BHP);

    const int tid = threadIdx.x, lane = tid & 31, w = tid >> 5;
    const int mg = w & 3, ng = w >> 2;          // 4 M-groups x 4 N-groups
    const int g4 = lane >> 2, c2 = (lane & 3) * 2;

    // ================= one-time prep =================
    // W rows reordered: n = ng*128 + g*32 + u  ->  global gate row g*128 + ng*32 + u
    for (int i = tid; i < 512 * KD; i += THREADS) {
        int n = i >> 7, k = i & 127;
        int grow = ((n >> 5) & 3) * 128 + (n >> 7) * 32 + (n & 31);
        *(__half*)(S + OFF_W + swz_off(n, k)) = __float2half_rn(w_hh[grow * 128 + k]);
    }
    if (tid < 512) {   // rank-2 folded dec_in weights + folded bias
        int n = tid;
        int grow = ((n >> 5) & 3) * 128 + (n >> 7) * 32 + (n & 31);
        float wx = 0.f, wy = 0.f, bz = b_ih[grow] + b_hh[grow];
        for (int e = 0; e < 64; e++) {
            float wv = w_ih[grow * 64 + e];
            wx = fmaf(wv, w_se[e * 2],     wx);
            wy = fmaf(wv, w_se[e * 2 + 1], wy);
            bz = fmaf(wv, b_se[e],         bz);
        }
        weff4[n] = make_float4(wx, wy, bz, 0.f);
    }
    if (tid < 256) whp[tid] = w_hp[tid];
    if (tid < 2)   bhp[tid] = b_hp[tid];

    // ldmatrix per-lane address components
    const uint32_t arow  = (uint32_t)(mg * 16 + (lane & 15));
    const uint32_t ax_   = arow & 7;
    const uint32_t asel  = (uint32_t)(lane >> 4);            // A k-chunk parity
    const uint32_t abase = Xs + arow * 256;
    const uint32_t bdn   = (uint32_t)((lane & 7) + ((lane >> 4) << 3));
    const uint32_t bbase = Sb + OFF_W + (uint32_t)(ng * 128 + bdn) * 256;
    const uint32_t bx_   = (uint32_t)(lane & 7);
    const uint32_t bk_   = (uint32_t)((lane >> 3) & 1);

    const int r0 = mg * 16 + g4;   // first owned ped row (second is r0+8)

    // ================= persistent tile loop =================
    for (int tile = blockIdx.x; tile < NTILES; tile += gridDim.x) {
        const int pedb = tile * M_TILE;
        __syncthreads();   // previous tile fully drained

        // ---- init: h0 -> X (fp16 swizzled), rel_buf = lpr, c0 -> regs ----
        for (int i = tid; i < 64 * 64; i += THREADS) {
            int r = i >> 6, kp = (i & 63) * 2;
            float2 hv = *(const float2*)(h0 + (size_t)(pedb + r) * 128 + kp);
            *(uint32_t*)(S + OFF_X + swz_off(r, kp)) = packh2(hv.x, hv.y);
        }
        if (tid < 64) relb[tid] = *(const float2*)(lpr + (size_t)(pedb + tid) * 2);

        float c_arr[16];
#pragma unroll
        for (int row = 0; row < 2; row++) {
            int gp = pedb + r0 + row * 8;
#pragma unroll
            for (int tu = 0; tu < 4; tu++) {
                int U0 = ng * 32 + tu * 8 + c2;
                float2 cv = *(const float2*)(c0 + (size_t)gp * 128 + U0);
                c_arr[tu * 4 + row]     = cv.x;
                c_arr[tu * 4 + 2 + row] = cv.y;
            }
        }
        __syncthreads();

        // ================= 12 recurrent steps =================
        for (int st = 0; st < STEPS; st++) {
            // ---- GEMM: gates += h @ Whh^T  (K=128, warp tile 16x128) ----
            float acc[16][4];
#pragma unroll
            for (int t = 0; t < 16; t++)
#pragma unroll
                for (int j = 0; j < 4; j++) acc[t][j] = 0.f;

            for (int kk = 0; kk < KK_STEPS; kk++) {
                uint32_t a0, a1, a2, a3;
                LDSM_X4(a0, a1, a2, a3, abase + ((((uint32_t)(2 * kk) + asel) ^ ax_) << 4));
#pragma unroll
                for (int t2 = 0; t2 < 8; t2++) {
                    uint32_t b0, b1, b2, b3;
                    LDSM_X4(b0, b1, b2, b3,
                            bbase + (uint32_t)t2 * 4096 +
                            ((((uint32_t)(2 * kk) + bk_) ^ bx_) << 4));
                    MMA16816(acc[2 * t2],     a0, a1, a2, a3, b0, b1);
                    MMA16816(acc[2 * t2 + 1], a0, a1, a2, a3, b2, b3);
                }
            }
            __syncthreads();   // all X reads done

            // ---- epilogue: rank-2 dec_in term + bias + LSTM, h -> X ----
            {
                float2 rl0 = relb[r0], rl1 = relb[r0 + 8];
                float ax0 = 0.f, ay0 = 0.f, ax1 = 0.f, ay1 = 0.f;
#pragma unroll
                for (int tu = 0; tu < 4; tu++) {
                    float hs[2][2];
#pragma unroll
                    for (int e = 0; e < 2; e++) {
                        int ul = tu * 8 + c2 + e;            // unit-local 0..31
                        int U  = ng * 32 + ul;               // global unit
                        float4 fi = weff4[ng * 128 + ul];
                        float4 ff = weff4[ng * 128 + 32 + ul];
                        float4 fg = weff4[ng * 128 + 64 + ul];
                        float4 fo = weff4[ng * 128 + 96 + ul];
                        float wx_ = whp[U], wy_ = whp[128 + U];
#pragma unroll
                        for (int row = 0; row < 2; row++) {
                            float rx = row ? rl1.x : rl0.x;
                            float ry = row ? rl1.y : rl0.y;
                            int reg = row * 2 + e;
                            float gi = acc[tu][reg]      + fi.z + rx * fi.x + ry * fi.y;
                            float gf = acc[4 + tu][reg]  + ff.z + rx * ff.x + ry * ff.y;
                            float gg = acc[8 + tu][reg]  + fg.z + rx * fg.x + ry * fg.y;
                            float go = acc[12 + tu][reg] + fo.z + rx * fo.x + ry * fo.y;
                            int ci = tu * 4 + e * 2 + row;
                            float cc = siga(gf) * c_arr[ci] + siga(gi) * tanhacc(gg);
                            c_arr[ci] = cc;
                            float h = siga(go) * tanhacc(cc);
                            if (row) { ax1 = fmaf(h, wx_, ax1); ay1 = fmaf(h, wy_, ay1); }
                            else     { ax0 = fmaf(h, wx_, ax0); ay0 = fmaf(h, wy_, ay0); }
                            hs[row][e] = h;
                        }
                    }
                    int k0 = ng * 32 + tu * 8 + c2;
#pragma unroll
                    for (int row = 0; row < 2; row++) {
                        int r = r0 + row * 8;
                        *(uint32_t*)(S + OFF_X + swz_off(r, k0)) = packh2(hs[row][0], hs[row][1]);
                    }
                }
                // butterfly over the 4 lanes of the quad (they share ped rows)
                ax0 += __shfl_xor_sync(~0u, ax0, 1); ax0 += __shfl_xor_sync(~0u, ax0, 2);
                ay0 += __shfl_xor_sync(~0u, ay0, 1); ay0 += __shfl_xor_sync(~0u, ay0, 2);
                ax1 += __shfl_xor_sync(~0u, ax1, 1); ax1 += __shfl_xor_sync(~0u, ax1, 2);
                ay1 += __shfl_xor_sync(~0u, ay1, 1); ay1 += __shfl_xor_sync(~0u, ay1, 2);
                if ((lane & 3) == 0) {
                    part[r0 * 8 + ng * 2]           = ax0;
                    part[r0 * 8 + ng * 2 + 1]       = ay0;
                    part[(r0 + 8) * 8 + ng * 2]     = ax1;
                    part[(r0 + 8) * 8 + ng * 2 + 1] = ay1;
                }
            }
            __syncthreads();

            // ---- rel = sum of 4 unit-group partials + b_hp; out; rel_buf ----
            if (tid < 64) {
                int r = tid;
                float rx = part[r * 8] + part[r * 8 + 2] + part[r * 8 + 4] +
                           part[r * 8 + 6] + bhp[0];
                float ry = part[r * 8 + 1] + part[r * 8 + 3] + part[r * 8 + 5] +
                           part[r * 8 + 7] + bhp[1];
                relb[r] = make_float2(rx, ry);
                out[(size_t)st * 65536 + pedb + r] = make_float2(rx, ry);
            }
            __syncthreads();
        }
    }
}

extern "C" void kernel_launch(void* const* d_in, const int* in_sizes, int n_in,
                              void* d_out, int out_size) {
    (void)in_sizes; (void)n_in; (void)out_size;
    const float* lpr  = (const float*)d_in[1];
    const float* h0   = (const float*)d_in[2];
    const float* c0   = (const float*)d_in[3];
    const float* w_ih = (const float*)d_in[4];
    const float* w_hh = (const float*)d_in[5];
    const float* b_ih = (const float*)d_in[6];
    const float* b_hh = (const float*)d_in[7];
    const float* w_se = (const float*)d_in[8];
    const float* b_se = (const float*)d_in[9];
    const float* w_hp = (const float*)d_in[10];
    const float* b_hp = (const float*)d_in[11];

    cudaFuncSetAttribute(decoder_mma, cudaFuncAttributeMaxDynamicSharedMemorySize, SMEM_BYTES);
    decoder_mma<<<GRID, THREADS, SMEM_BYTES>>>(lpr, h0, c0, w_ih, w_hh, b_ih, b_hh,
                                               w_se, b_se, w_hp, b_hp, (float2*)d_out);
}

// round 4
// speedup vs baseline: 7.6332x; 1.2061x over previous
#include <cuda_runtime.h>
#include <cuda_fp16.h>
#include <cstdint>
#include <cstddef>

#define THREADS 512
#define M_TILE  64
#define NTILES  1024          // 65536 / 64
#define GRID    148
#define STEPS   12
#define KD      128
#define KK_STEPS 8

// ---- smem layout (bytes from dynamic base) ----
#define OFF_W    0            // 512 rows * 256B fp16 swizzled  = 131072
#define OFF_X    131072       // 2 x (64 rows * 256B) ping-pong =  32768
#define XBUF_BYTES 16384
#define OFF_WEFF 163840       // float4[512]                    =   8192
#define OFF_WHP  172032       // float[256]                     =   1024
#define OFF_PART 173056       // float[64][18]                  =   4608
#define OFF_REL  177664       // float2[64]                     =    512
#define OFF_BHP  178176       // float[2]                       =      8
#define SMEM_BYTES 178304

__device__ __forceinline__ uint32_t smem_u32(const void* p) {
    uint32_t a;
    asm("{ .reg .u64 t; cvta.to.shared.u64 t, %1; cvt.u32.u64 %0, t; }" : "=r"(a) : "l"(p));
    return a;
}
__device__ __forceinline__ uint32_t packh2(float lo, float hi) {
    uint32_t r; asm("cvt.rn.f16x2.f32 %0, %1, %2;" : "=r"(r) : "f"(hi), "f"(lo)); return r;
}
__device__ __forceinline__ float tanh_ap(float x) {
    float y; asm("tanh.approx.f32 %0, %1;" : "=f"(y) : "f"(x)); return y;
}
__device__ __forceinline__ float siga(float x) { return fmaf(tanh_ap(0.5f * x), 0.5f, 0.5f); }

#define LDSM_X4(r0, r1, r2, r3, addr)                                                  \
    asm volatile("ldmatrix.sync.aligned.m8n8.x4.shared.b16 {%0,%1,%2,%3}, [%4];"       \
                 : "=r"(r0), "=r"(r1), "=r"(r2), "=r"(r3) : "r"(addr))

#define MMA16816(d, a0, a1, a2, a3, b0, b1)                                            \
    asm volatile("mma.sync.aligned.m16n8k16.row.col.f32.f16.f16.f32 "                  \
                 "{%0,%1,%2,%3}, {%4,%5,%6,%7}, {%8,%9}, {%0,%1,%2,%3};"               \
                 : "+f"((d)[0]), "+f"((d)[1]), "+f"((d)[2]), "+f"((d)[3])              \
                 : "r"(a0), "r"(a1), "r"(a2), "r"(a3), "r"(b0), "r"(b1))

// swizzled byte offset within a 256B-row fp16 tile
__device__ __forceinline__ uint32_t swz_off(int r, int k) {
    return (uint32_t)(r * 256 + ((((k >> 3) ^ (r & 7)) << 4) | ((k & 7) * 2)));
}

__global__ __launch_bounds__(THREADS, 1)
void decoder_mma(const float* __restrict__ lpr, const float* __restrict__ h0,
                 const float* __restrict__ c0,
                 const float* __restrict__ w_ih, const float* __restrict__ w_hh,
                 const float* __restrict__ b_ih, const float* __restrict__ b_hh,
                 const float* __restrict__ w_se, const float* __restrict__ b_se,
                 const float* __restrict__ w_hp, const float* __restrict__ b_hp,
                 float2* __restrict__ out)
{
    extern __shared__ char S[];
    const uint32_t Sb = smem_u32(S);
    float4* weff4 = (float4*)(S + OFF_WEFF);
    float*  whp   = (float*)(S + OFF_WHP);
    float*  part  = (float*)(S + OFF_PART);   // [64][18]
    float2* relb  = (float2*)(S + OFF_REL);
    float*  bhp   = (float*)(S + OFF_BHP);

    const int tid = threadIdx.x, lane = tid & 31, w = tid >> 5;
    const int mg = w & 1, ng = w >> 1;        // 2 M-groups x 8 N-groups, warp m32n64
    const int g4 = lane >> 2, c2 = (lane & 3) * 2;

    // ================= one-time prep =================
    // W row reorder: n = ng*64 + gate*16 + ul  ->  global gate row gate*128 + ng*16 + ul
    for (int i = tid; i < 512 * KD; i += THREADS) {
        int n = i >> 7, k = i & 127;
        int grow = ((n >> 4) & 3) * 128 + (n >> 6) * 16 + (n & 15);
        *(__half*)(S + OFF_W + swz_off(n, k)) = __float2half_rn(w_hh[grow * 128 + k]);
    }
    if (tid < 512) {   // rank-2 folded dec_in weights + folded bias (fp32-exact path)
        int n = tid;
        int grow = ((n >> 4) & 3) * 128 + (n >> 6) * 16 + (n & 15);
        float wx = 0.f, wy = 0.f, bz = b_ih[grow] + b_hh[grow];
        for (int e = 0; e < 64; e++) {
            float wv = w_ih[grow * 64 + e];
            wx = fmaf(wv, w_se[e * 2],     wx);
            wy = fmaf(wv, w_se[e * 2 + 1], wy);
            bz = fmaf(wv, b_se[e],         bz);
        }
        weff4[n] = make_float4(wx, wy, bz, 0.f);
    }
    if (tid < 256) whp[tid] = w_hp[tid];
    if (tid < 2)   bhp[tid] = b_hp[tid];

    // ldmatrix per-lane address components
    const uint32_t ax_    = (uint32_t)(lane & 7);
    const uint32_t asel   = (uint32_t)(lane >> 4);
    const uint32_t arowoff = (uint32_t)(mg * 32 + (lane & 15)) * 256;
    const uint32_t bdn    = (uint32_t)((lane & 7) + ((lane >> 4) << 3));
    const uint32_t bbase  = Sb + OFF_W + (uint32_t)(ng * 64 + bdn) * 256;
    const uint32_t bk_    = (uint32_t)((lane >> 3) & 1);

    // ================= persistent tile loop =================
    for (int tile = blockIdx.x; tile < NTILES; tile += gridDim.x) {
        const int pedb = tile * M_TILE;
        __syncthreads();   // previous tile fully drained

        // ---- init: h0 -> X buffer 0, relb = lpr, c0 -> regs ----
        for (int i = tid; i < 64 * 64; i += THREADS) {
            int r = i >> 6, kp = (i & 63) * 2;
            float2 hv = *(const float2*)(h0 + (size_t)(pedb + r) * 128 + kp);
            *(uint32_t*)(S + OFF_X + swz_off(r, kp)) = packh2(hv.x, hv.y);
        }
        if (tid < 64) relb[tid] = *(const float2*)(lpr + (size_t)(pedb + tid) * 2);

        float c_arr[16];   // [mt][up8][e][row8]
#pragma unroll
        for (int mt = 0; mt < 2; mt++)
#pragma unroll
            for (int up8 = 0; up8 < 2; up8++)
#pragma unroll
                for (int row8 = 0; row8 < 2; row8++) {
                    int gp = pedb + mg * 32 + mt * 16 + g4 + row8 * 8;
                    int U0 = ng * 16 + up8 * 8 + c2;
                    float2 cv = *(const float2*)(c0 + (size_t)gp * 128 + U0);
                    c_arr[mt * 8 + up8 * 4 + row8]     = cv.x;
                    c_arr[mt * 8 + up8 * 4 + 2 + row8] = cv.y;
                }
        __syncthreads();

        int par = 0;
        // ================= 12 recurrent steps =================
        for (int st = 0; st < STEPS; st++) {
            const uint32_t abase = Sb + OFF_X + (uint32_t)par * XBUF_BYTES + arowoff;
            const uint32_t xw    = (uint32_t)(par ^ 1) * XBUF_BYTES;

            // ---- GEMM: gates = h @ Whh^T, warp tile m32 x n64, K=128 ----
            float acc[2][8][4];
#pragma unroll
            for (int mt = 0; mt < 2; mt++)
#pragma unroll
                for (int nt = 0; nt < 8; nt++)
#pragma unroll
                    for (int j = 0; j < 4; j++) acc[mt][nt][j] = 0.f;

#pragma unroll
            for (int kk = 0; kk < KK_STEPS; kk++) {
                const uint32_t koff = (((uint32_t)(2 * kk) + asel) ^ ax_) << 4;
                uint32_t a0[4], a1[4];
                LDSM_X4(a0[0], a0[1], a0[2], a0[3], abase + koff);
                LDSM_X4(a1[0], a1[1], a1[2], a1[3], abase + 4096 + koff);
                const uint32_t bkoff = (((uint32_t)(2 * kk) + bk_) ^ ax_) << 4;
#pragma unroll
                for (int t2 = 0; t2 < 4; t2++) {
                    uint32_t b0, b1, b2, b3;
                    LDSM_X4(b0, b1, b2, b3, bbase + (uint32_t)t2 * 4096 + bkoff);
                    MMA16816(acc[0][2 * t2],     a0[0], a0[1], a0[2], a0[3], b0, b1);
                    MMA16816(acc[0][2 * t2 + 1], a0[0], a0[1], a0[2], a0[3], b2, b3);
                    MMA16816(acc[1][2 * t2],     a1[0], a1[1], a1[2], a1[3], b0, b1);
                    MMA16816(acc[1][2 * t2 + 1], a1[0], a1[1], a1[2], a1[3], b2, b3);
                }
            }

            // ---- epilogue: rank-2 dec_in + bias + LSTM; new h -> other X buf ----
            float2 rl[2][2];
#pragma unroll
            for (int mt = 0; mt < 2; mt++) {
                rl[mt][0] = relb[mg * 32 + mt * 16 + g4];
                rl[mt][1] = relb[mg * 32 + mt * 16 + g4 + 8];
            }
            float axs[2][2] = {{0.f, 0.f}, {0.f, 0.f}};
            float ays[2][2] = {{0.f, 0.f}, {0.f, 0.f}};
#pragma unroll
            for (int mt = 0; mt < 2; mt++) {
#pragma unroll
                for (int up8 = 0; up8 < 2; up8++) {
                    float hp[2][2];   // [row8][e]
#pragma unroll
                    for (int e = 0; e < 2; e++) {
                        int ul = up8 * 8 + c2 + e;
                        float4 fi = weff4[ng * 64 + ul];
                        float4 ff = weff4[ng * 64 + 16 + ul];
                        float4 fg = weff4[ng * 64 + 32 + ul];
                        float4 fo = weff4[ng * 64 + 48 + ul];
                        float wx_ = whp[ng * 16 + ul], wy_ = whp[128 + ng * 16 + ul];
#pragma unroll
                        for (int row8 = 0; row8 < 2; row8++) {
                            float rx = rl[mt][row8].x, ry = rl[mt][row8].y;
                            int reg = row8 * 2 + e;
                            float gi = acc[mt][up8][reg]     + fi.z + rx * fi.x + ry * fi.y;
                            float gf = acc[mt][2 + up8][reg] + ff.z + rx * ff.x + ry * ff.y;
                            float gg = acc[mt][4 + up8][reg] + fg.z + rx * fg.x + ry * fg.y;
                            float go = acc[mt][6 + up8][reg] + fo.z + rx * fo.x + ry * fo.y;
                            int ci = mt * 8 + up8 * 4 + e * 2 + row8;
                            float cc = siga(gf) * c_arr[ci] + siga(gi) * tanh_ap(gg);
                            c_arr[ci] = cc;
                            float h = siga(go) * tanh_ap(cc);
                            axs[mt][row8] = fmaf(h, wx_, axs[mt][row8]);
                            ays[mt][row8] = fmaf(h, wy_, ays[mt][row8]);
                            hp[row8][e] = h;
                        }
                    }
                    int k0 = ng * 16 + up8 * 8 + c2;
#pragma unroll
                    for (int row8 = 0; row8 < 2; row8++) {
                        int r = mg * 32 + mt * 16 + g4 + row8 * 8;
                        *(uint32_t*)(S + OFF_X + xw + swz_off(r, k0)) =
                            packh2(hp[row8][0], hp[row8][1]);
                    }
                }
            }
            // butterfly over the 4 lanes of the quad (same peds, different units)
#pragma unroll
            for (int mt = 0; mt < 2; mt++)
#pragma unroll
                for (int row8 = 0; row8 < 2; row8++) {
                    float& ax = axs[mt][row8];
                    float& ay = ays[mt][row8];
                    ax += __shfl_xor_sync(~0u, ax, 1); ax += __shfl_xor_sync(~0u, ax, 2);
                    ay += __shfl_xor_sync(~0u, ay, 1); ay += __shfl_xor_sync(~0u, ay, 2);
                }
            if ((lane & 3) == 0) {
#pragma unroll
                for (int mt = 0; mt < 2; mt++)
#pragma unroll
                    for (int row8 = 0; row8 < 2; row8++) {
                        int r = mg * 32 + mt * 16 + g4 + row8 * 8;
                        *(float2*)(part + r * 18 + ng * 2) =
                            make_float2(axs[mt][row8], ays[mt][row8]);
                    }
            }
            __syncthreads();

            // ---- rel = sum over 8 N-groups + b_hp; emit; feed back ----
            if (tid < 64) {
                const float* pr = part + tid * 18;
                float rx = pr[0] + pr[2] + pr[4] + pr[6] + pr[8] + pr[10] + pr[12] + pr[14] + bhp[0];
                float ry = pr[1] + pr[3] + pr[5] + pr[7] + pr[9] + pr[11] + pr[13] + pr[15] + bhp[1];
                relb[tid] = make_float2(rx, ry);
                out[(size_t)st * 65536 + pedb + tid] = make_float2(rx, ry);
            }
            __syncthreads();
            par ^= 1;
        }
    }
}

extern "C" void kernel_launch(void* const* d_in, const int* in_sizes, int n_in,
                              void* d_out, int out_size) {
    (void)in_sizes; (void)n_in; (void)out_size;
    const float* lpr  = (const float*)d_in[1];
    const float* h0   = (const float*)d_in[2];
    const float* c0   = (const float*)d_in[3];
    const float* w_ih = (const float*)d_in[4];
    const float* w_hh = (const float*)d_in[5];
    const float* b_ih = (const float*)d_in[6];
    const float* b_hh = (const float*)d_in[7];
    const float* w_se = (const float*)d_in[8];
    const float* b_se = (const float*)d_in[9];
    const float* w_hp = (const float*)d_in[10];
    const float* b_hp = (const float*)d_in[11];

    cudaFuncSetAttribute(decoder_mma, cudaFuncAttributeMaxDynamicSharedMemorySize, SMEM_BYTES);
    decoder_mma<<<GRID, THREADS, SMEM_BYTES>>>(lpr, h0, c0, w_ih, w_hh, b_ih, b_hh,
                                               w_se, b_se, w_hp, b_hp, (float2*)d_out);
}